// round 11
// baseline (speedup 1.0000x reference)
#include <cuda_runtime.h>
#include <cuda_bf16.h>
#include <math.h>
#include <stdint.h>

#define EMB   512
#define BATCH 512
#define M_C   0.4f
#define H_C   0.333f
#define S_C   64.0f
#define EPS_C 1.0e-3f
#define PI_C  3.14159265358979323846f

#define BM  128
#define BN  64
#define BK  64
#define NT  256
#define KCH 8            // 512 / 64
#define NPAD 70784       // N rounded up to 64

// dynamic smem layout (bytes); stage = 48KB, total 105472 -> 2 CTAs/SM
#define SM_AH(s) ((s) * 49152 + 0)       // A hi 16KB
#define SM_AL(s) ((s) * 49152 + 16384)   // A lo 16KB
#define SM_BH(s) ((s) * 49152 + 32768)   // B hi 8KB
#define SM_BL(s) ((s) * 49152 + 40960)   // B lo 8KB
#define SM_INV   99328
#define SM_LAB   99840
#define SM_GANG  100352
#define SM_GADD  100864
#define SM_AMX   101376                  // 512 * 8B
#define SMEM_BYTES 105472

#define SWZ(x) ((x) ^ (((x) >> 3) & 0x70))   // 128B-row XOR swizzle

__device__ float d_gang[BATCH];
__device__ float d_gadd[BATCH];
__device__ float d_ms[BATCH];
__device__ unsigned long long d_arg[BATCH];
__device__ float d_invn[NPAD];
__device__ __align__(16) unsigned short d_Ah[BATCH * EMB];      // bf16 hi of emb
__device__ __align__(16) unsigned short d_Al[BATCH * EMB];      // bf16 lo of emb
__device__ __align__(16) unsigned short d_Bh[(size_t)NPAD * EMB]; // B hi, [col][k]
__device__ __align__(16) unsigned short d_Bl[(size_t)NPAD * EMB]; // B lo, [col][k]

// ---------------------------------------------------------------------------
__device__ __forceinline__ uint32_t smem_u32(const void* p) {
    uint32_t a;
    asm("{ .reg .u64 t; cvta.to.shared.u64 t, %1; cvt.u32.u64 %0, t; }"
        : "=r"(a) : "l"(p));
    return a;
}
__device__ __forceinline__ void cp16(uint32_t dst, const void* src) {
    asm volatile("cp.async.cg.shared.global [%0], [%1], 16;"
                 :: "r"(dst), "l"(src) : "memory");
}
#define CP_COMMIT() asm volatile("cp.async.commit_group;" ::: "memory")
#define CP_WAIT0()  asm volatile("cp.async.wait_group 0;" ::: "memory")

#define LDSM4(r, a) \
    asm volatile("ldmatrix.sync.aligned.m8n8.x4.shared.b16 {%0,%1,%2,%3}, [%4];" \
        : "=r"((r)[0]), "=r"((r)[1]), "=r"((r)[2]), "=r"((r)[3]) : "r"(a))

// b0 = (n-subgroup, k0-7) frag, b1 = (n-subgroup, k8-15) frag
__device__ __forceinline__ void mma16816(float* c, const uint32_t* a,
                                         uint32_t b0, uint32_t b1) {
    asm volatile(
        "mma.sync.aligned.m16n8k16.row.col.f32.bf16.bf16.f32 "
        "{%0,%1,%2,%3}, {%4,%5,%6,%7}, {%8,%9}, {%0,%1,%2,%3};"
        : "+f"(c[0]), "+f"(c[1]), "+f"(c[2]), "+f"(c[3])
        : "r"(a[0]), "r"(a[1]), "r"(a[2]), "r"(a[3]), "r"(b0), "r"(b1));
}

// two-level bf16 split of a pair of floats, packed as bf16x2
__device__ __forceinline__ void split2(float x0, float x1,
                                       uint32_t& hp, uint32_t& lp) {
    asm("cvt.rn.bf16x2.f32 %0, %1, %2;" : "=r"(hp) : "f"(x1), "f"(x0));
    float h0 = __uint_as_float(hp << 16);
    float h1 = __uint_as_float(hp & 0xffff0000u);
    float l0 = x0 - h0, l1 = x1 - h1;
    asm("cvt.rn.bf16x2.f32 %0, %1, %2;" : "=r"(lp) : "f"(l1), "f"(l0));
}
// single-value split (same rounding as split2)
__device__ __forceinline__ void split1(float x, unsigned short& h,
                                       unsigned short& l) {
    __nv_bfloat16 hb = __float2bfloat16(x);
    float hf = __bfloat162float(hb);
    __nv_bfloat16 lb = __float2bfloat16(x - hf);
    h = *reinterpret_cast<unsigned short*>(&hb);
    l = *reinterpret_cast<unsigned short*>(&lb);
}

// ---------------------------------------------------------------------------
// Kernel 1: fused prep — block 128: stats + resets; blocks 0..127: A split
// ---------------------------------------------------------------------------
__global__ void prep_kernel(const float* __restrict__ norms,
                            const float* __restrict__ A) {
    if (blockIdx.x == 128) {
        __shared__ float red[BATCH];
        int t = threadIdx.x;
        float x = fminf(fmaxf(norms[t], 0.001f), 100.0f);
        red[t] = x;
        __syncthreads();
        for (int s = BATCH / 2; s > 0; s >>= 1) {
            if (t < s) red[t] += red[t + s];
            __syncthreads();
        }
        float mean = red[0] * (1.0f / BATCH);
        __syncthreads();
        float dv = x - mean;
        red[t] = dv * dv;
        __syncthreads();
        for (int s = BATCH / 2; s > 0; s >>= 1) {
            if (t < s) red[t] += red[t + s];
            __syncthreads();
        }
        float stdv = sqrtf(red[0] / (float)(BATCH - 1));  // ddof=1
        float ms = fminf(fmaxf((x - mean) / (stdv + EPS_C) * H_C, -1.0f), 1.0f);
        d_ms[t]   = ms;
        d_gang[t] = -M_C * ms;
        d_gadd[t] = M_C + M_C * ms;
        d_arg[t]  = 0ull;
    } else {
        int i = blockIdx.x * 512 + threadIdx.x;  // 65536 float4s
        float4 v = ((const float4*)A)[i];
        uint32_t h0, l0, h1, l1;
        split2(v.x, v.y, h0, l0);
        split2(v.z, v.w, h1, l1);
        ((uint2*)d_Ah)[i] = make_uint2(h0, h1);
        ((uint2*)d_Al)[i] = make_uint2(l0, l1);
    }
}

// ---------------------------------------------------------------------------
// Kernel 1b: transpose+split B -> d_Bh/d_Bl [col][k] K-major; column inv-norms
// ---------------------------------------------------------------------------
__global__ void __launch_bounds__(256)
bsplit_kernel(const float* __restrict__ B, int N) {
    __shared__ __align__(16) unsigned short sh[64][68];  // stride 136B
    __shared__ __align__(16) unsigned short sl[64][68];
    __shared__ float red[256];
    const int tid = threadIdx.x;
    const int c0  = blockIdx.x * 64;
    const int ncl = tid & 63;       // column within tile
    const int rg  = tid >> 6;       // row group 0..3
    const int col = c0 + ncl;
    const bool cvv = col < N;
    float sumsq = 0.0f;

    for (int rc = 0; rc < 8; rc++) {
        // load 64 rows x 64 cols (coalesced), split, transpose into smem
#pragma unroll
        for (int r = 0; r < 16; r++) {
            const int rl  = rg * 16 + r;
            const int row = rc * 64 + rl;
            float v = cvv ? __ldg(B + (size_t)row * N + col) : 0.0f;
            sumsq += v * v;
            unsigned short h, l;
            split1(v, h, l);
            sh[ncl][rl] = h;
            sl[ncl][rl] = l;
        }
        __syncthreads();
        // write out [col][k] runs: thread -> (col = tid>>2, 16 k's at (tid&3)*16)
        {
            const int cw = tid >> 2;
            const int kc = (tid & 3) * 16;
            const unsigned short* s1 = &sh[cw][kc];
            const unsigned short* s2 = &sl[cw][kc];
            uint2 a0 = *(const uint2*)(s1 + 0), a1 = *(const uint2*)(s1 + 4);
            uint2 a2 = *(const uint2*)(s1 + 8), a3 = *(const uint2*)(s1 + 12);
            uint2 b0 = *(const uint2*)(s2 + 0), b1 = *(const uint2*)(s2 + 4);
            uint2 b2 = *(const uint2*)(s2 + 8), b3 = *(const uint2*)(s2 + 12);
            unsigned short* dh = d_Bh + (size_t)(c0 + cw) * EMB + rc * 64 + kc;
            unsigned short* dl = d_Bl + (size_t)(c0 + cw) * EMB + rc * 64 + kc;
            *(uint4*)(dh)     = make_uint4(a0.x, a0.y, a1.x, a1.y);
            *(uint4*)(dh + 8) = make_uint4(a2.x, a2.y, a3.x, a3.y);
            *(uint4*)(dl)     = make_uint4(b0.x, b0.y, b1.x, b1.y);
            *(uint4*)(dl + 8) = make_uint4(b2.x, b2.y, b3.x, b3.y);
        }
        __syncthreads();
    }
    // column inv-norms
    red[tid] = sumsq;
    __syncthreads();
    if (tid < 64) {
        float s = red[tid] + red[tid + 64] + red[tid + 128] + red[tid + 192];
        d_invn[c0 + tid] = rsqrtf(fmaxf(s, 1e-30f));
    }
}

// ---------------------------------------------------------------------------
// Kernel 2: HMMA 3-split GEMM, all-cp.async feed (2 CTAs/SM) + margins + argmax
// ---------------------------------------------------------------------------
__global__ void __launch_bounds__(NT, 2)
gemm_kernel(const int* __restrict__ label,
            float* __restrict__ out1, float* __restrict__ out2, int N)
{
    extern __shared__ char smem[];
    const uint32_t sb = smem_u32(smem);
    const int tid  = threadIdx.x;
    const int wid  = tid >> 5, lane = tid & 31;
    const int wm   = wid & 1;        // m half (64 rows)
    const int wn   = wid >> 1;       // n quarter (16 cols)
    const int m0   = blockIdx.x * BM;
    const int n0   = blockIdx.y * BN;

    int*   lab_s  = (int*)(smem + SM_LAB);
    float* gang_s = (float*)(smem + SM_GANG);
    float* gadd_s = (float*)(smem + SM_GADD);
    float* invn_s = (float*)(smem + SM_INV);
    unsigned long long* amx = (unsigned long long*)(smem + SM_AMX);

    if (tid < BM) {
        lab_s[tid]  = label[m0 + tid];
        gang_s[tid] = d_gang[m0 + tid];
        gadd_s[tid] = d_gadd[m0 + tid];
    }
    if (tid < BN) invn_s[tid] = d_invn[n0 + tid];

    auto cpStage = [&](int c, int s) {
        // A: 128 rows x 128B (hi+lo) = 8 chunks/thread
#pragma unroll
        for (int q = 0; q < 4; q++) {
            int id = q * 256 + tid;
            int row = id >> 3, ch = id & 7;
            uint32_t off = SWZ(row * 128 + ch * 16);
            const size_t g = (size_t)(m0 + row) * EMB + c * BK + ch * 8;
            cp16(sb + SM_AH(s) + off, d_Ah + g);
            cp16(sb + SM_AL(s) + off, d_Al + g);
        }
        // B: 64 cols x 128B (hi+lo) = 4 chunks/thread  (K-major pre-split)
#pragma unroll
        for (int q = 0; q < 2; q++) {
            int id = q * 256 + tid;
            int row = id >> 3, ch = id & 7;
            uint32_t off = SWZ(row * 128 + ch * 16);
            const size_t g = (size_t)(n0 + row) * EMB + c * BK + ch * 8;
            cp16(sb + SM_BH(s) + off, d_Bh + g);
            cp16(sb + SM_BL(s) + off, d_Bl + g);
        }
        CP_COMMIT();
    };

    // prologue
    cpStage(0, 0);
    CP_WAIT0();
    __syncthreads();

    float acc[4][2][4];
#pragma unroll
    for (int i = 0; i < 4; i++)
#pragma unroll
        for (int j = 0; j < 2; j++)
#pragma unroll
            for (int e = 0; e < 4; e++) acc[i][j][e] = 0.0f;

    // ldmatrix lane address pattern (16 rows x 32B k-window)
    const int arow = ((lane >> 3) & 1) * 8 + (lane & 7);
    const int akb  = (lane >> 4) * 16;

    for (int c = 0; c < KCH; c++) {
        const int s = c & 1, s2 = (c + 1) & 1;
        if (c < KCH - 1) cpStage(c + 1, s2);
#pragma unroll
        for (int ks = 0; ks < 4; ks++) {
            // batch-load ALL frags for this k-step, then issue MMAs
            // LDSM4: r0=(lo8,kLo) r1=(hi8,kLo) r2=(lo8,kHi) r3=(hi8,kHi)
            uint32_t bh[4], bl[4];
            {
                uint32_t off = SWZ((wn * 16 + arow) * 128 + ks * 32 + akb);
                LDSM4(bh, sb + SM_BH(s) + off);
                LDSM4(bl, sb + SM_BL(s) + off);
            }
            uint32_t ah[4][4], al[4][4];
#pragma unroll
            for (int i = 0; i < 4; i++) {
                uint32_t off = SWZ((wm * 64 + i * 16 + arow) * 128 + ks * 32 + akb);
                LDSM4(ah[i], sb + SM_AH(s) + off);
                LDSM4(al[i], sb + SM_AL(s) + off);
            }
            // term-major: accumulator chain distance = 8
#pragma unroll
            for (int i = 0; i < 4; i++)
#pragma unroll
                for (int j = 0; j < 2; j++)
                    mma16816(acc[i][j], ah[i], bh[j], bh[j + 2]);
#pragma unroll
            for (int i = 0; i < 4; i++)
#pragma unroll
                for (int j = 0; j < 2; j++)
                    mma16816(acc[i][j], ah[i], bl[j], bl[j + 2]);
#pragma unroll
            for (int i = 0; i < 4; i++)
#pragma unroll
                for (int j = 0; j < 2; j++)
                    mma16816(acc[i][j], al[i], bh[j], bh[j + 2]);
        }
        if (c < KCH - 1) CP_WAIT0();
        __syncthreads();
    }

    // ---- epilogue: margins + stores + argmax ----
#pragma unroll
    for (int i = 0; i < 4; i++) {
        const int r0 = wm * 64 + i * 16 + (lane >> 2);
#pragma unroll
        for (int rh = 0; rh < 2; rh++) {
            const int row = r0 + rh * 8;
            const int gm  = m0 + row;
            const int lab   = lab_s[row];
            const float gng = gang_s[row];
            const float gad = gadd_s[row];
            unsigned long long best = 0ull;
#pragma unroll
            for (int j = 0; j < 2; j++) {
                const int cl0 = wn * 16 + j * 8 + (lane & 3) * 2;
                const int gc0 = n0 + cl0;
                float o1v[2], o2v[2];
#pragma unroll
                for (int e = 0; e < 2; e++) {
                    float v = acc[i][j][rh * 2 + e] * invn_s[cl0 + e];
                    float cosv = fminf(fmaxf(v, -1.0f + EPS_C), 1.0f - EPS_C);
                    float vm = cosv, o1 = cosv * S_C;
                    if (gc0 + e == lab) {  // clip(acos+g) identity off-label
                        float th = fminf(fmaxf(acosf(cosv) + gng, EPS_C),
                                         PI_C - EPS_C);
                        vm = cosf(th);
                        o1 = (vm - gad) * S_C;
                    }
                    o1v[e] = o1;
                    o2v[e] = vm * S_C;
                    if (gc0 + e < N) {
                        unsigned u = __float_as_uint(vm);
                        u = (u & 0x80000000u) ? ~u : (u | 0x80000000u);
                        unsigned long long key =
                            ((unsigned long long)u << 32) |
                            (unsigned)(~(unsigned)(gc0 + e));
                        best = best > key ? best : key;
                    }
                }
                if (gc0 + 1 < N) {
                    const size_t gb = (size_t)gm * N + gc0;
                    __stcs((float2*)(out1 + gb), make_float2(o1v[0], o1v[1]));
                    __stcs((float2*)(out2 + gb), make_float2(o2v[0], o2v[1]));
                }
            }
            unsigned long long o = __shfl_xor_sync(0xFFFFFFFFu, best, 1);
            best = best > o ? best : o;
            o = __shfl_xor_sync(0xFFFFFFFFu, best, 2);
            best = best > o ? best : o;
            if ((lane & 3) == 0) amx[row * 4 + wn] = best;
        }
    }
    __syncthreads();
    if (tid < BM) {
        unsigned long long b0 = amx[tid * 4 + 0], b1 = amx[tid * 4 + 1];
        unsigned long long b2 = amx[tid * 4 + 2], b3 = amx[tid * 4 + 3];
        unsigned long long b = b0 > b1 ? b0 : b1;
        b = b > b2 ? b : b2;
        b = b > b3 ? b : b3;
        atomicMax(&d_arg[m0 + tid], b);
    }
}

// ---------------------------------------------------------------------------
// Kernel 3: second margin at per-row argmax; write argmax/ms outputs
// ---------------------------------------------------------------------------
__global__ void fixup_kernel(float* __restrict__ out2,
                             float* __restrict__ oarg,
                             float* __restrict__ oms, int N) {
    int b = threadIdx.x;
    unsigned long long key = d_arg[b];
    unsigned hi = (unsigned)(key >> 32);
    unsigned lo = (unsigned)key;
    int col = (int)(~lo);
    float v = (hi & 0x80000000u) ? __uint_as_float(hi & 0x7FFFFFFFu)
                                 : __uint_as_float(~hi);
    float th = fminf(fmaxf(acosf(v) + d_gang[b], EPS_C), PI_C - EPS_C);
    out2[(size_t)b * N + col] = (cosf(th) - d_gadd[b]) * S_C;
    oarg[b] = (float)col;
    oms[b]  = d_ms[b];
}

// ---------------------------------------------------------------------------
extern "C" void kernel_launch(void* const* d_in, const int* in_sizes, int n_in,
                              void* d_out, int out_size) {
    const float* emb   = (const float*)d_in[0];
    const float* norms = (const float*)d_in[1];
    const int*   label = (const int*)d_in[2];
    const float* kern  = (const float*)d_in[3];
    int N = in_sizes[3] / EMB;

    float* out1 = (float*)d_out;
    float* out2 = out1 + (size_t)BATCH * N;
    float* oarg = out2 + (size_t)BATCH * N;
    float* oms  = oarg + BATCH;

    cudaFuncSetAttribute(gemm_kernel,
                         cudaFuncAttributeMaxDynamicSharedMemorySize, SMEM_BYTES);

    prep_kernel<<<129, 512>>>(norms, emb);
    bsplit_kernel<<<(N + 63) / 64, 256>>>(kern, N);
    dim3 grid(BATCH / BM, (N + BN - 1) / BN);   // x = M fast -> B tile L2 reuse
    gemm_kernel<<<grid, NT, SMEM_BYTES>>>(label, out1, out2, N);
    fixup_kernel<<<1, BATCH>>>(out2, oarg, oms, N);
}

// round 12
// speedup vs baseline: 1.1302x; 1.1302x over previous
#include <cuda_runtime.h>
#include <cuda_bf16.h>
#include <math.h>
#include <stdint.h>

#define EMB   512
#define BATCH 512
#define M_C   0.4f
#define H_C   0.333f
#define S_C   64.0f
#define EPS_C 1.0e-3f
#define PI_C  3.14159265358979323846f

#define BM  128
#define BN  64
#define BK  64
#define NT  256
#define KCH 8          // 512 / 64

// dynamic smem layout (bytes); stage = 48KB, total 105472 -> 2 CTAs/SM
#define SM_AH(s) ((s) * 49152 + 0)       // A hi 16KB
#define SM_AL(s) ((s) * 49152 + 16384)   // A lo 16KB
#define SM_BH(s) ((s) * 49152 + 32768)   // B hi 8KB
#define SM_BL(s) ((s) * 49152 + 40960)   // B lo 8KB
#define SM_RED   98304
#define SM_INV   99328
#define SM_LAB   99840
#define SM_GANG  100352
#define SM_GADD  100864
#define SM_AMX   101376                  // 256 * 8B
#define SMEM_BYTES 105472

#define SWZ(x) ((x) ^ (((x) >> 3) & 0x70))   // 128B-row XOR swizzle

__device__ float d_gang[BATCH];
__device__ float d_gadd[BATCH];
__device__ float d_ms[BATCH];
__device__ unsigned long long d_arg[BATCH];
__device__ __align__(16) unsigned short d_Ah[BATCH * EMB];  // bf16 hi of emb
__device__ __align__(16) unsigned short d_Al[BATCH * EMB];  // bf16 lo of emb

// ---------------------------------------------------------------------------
__device__ __forceinline__ uint32_t smem_u32(const void* p) {
    uint32_t a;
    asm("{ .reg .u64 t; cvta.to.shared.u64 t, %1; cvt.u32.u64 %0, t; }"
        : "=r"(a) : "l"(p));
    return a;
}
__device__ __forceinline__ void cp16(uint32_t dst, const void* src) {
    asm volatile("cp.async.cg.shared.global [%0], [%1], 16;"
                 :: "r"(dst), "l"(src) : "memory");
}
#define CP_COMMIT() asm volatile("cp.async.commit_group;" ::: "memory")
#define CP_WAIT0()  asm volatile("cp.async.wait_group 0;" ::: "memory")

#define LDSM4(r, a) \
    asm volatile("ldmatrix.sync.aligned.m8n8.x4.shared.b16 {%0,%1,%2,%3}, [%4];" \
        : "=r"((r)[0]), "=r"((r)[1]), "=r"((r)[2]), "=r"((r)[3]) : "r"(a))

// b0 = (n-subgroup, k0-7) frag, b1 = (n-subgroup, k8-15) frag
__device__ __forceinline__ void mma16816(float* c, const uint32_t* a,
                                         uint32_t b0, uint32_t b1) {
    asm volatile(
        "mma.sync.aligned.m16n8k16.row.col.f32.bf16.bf16.f32 "
        "{%0,%1,%2,%3}, {%4,%5,%6,%7}, {%8,%9}, {%0,%1,%2,%3};"
        : "+f"(c[0]), "+f"(c[1]), "+f"(c[2]), "+f"(c[3])
        : "r"(a[0]), "r"(a[1]), "r"(a[2]), "r"(a[3]), "r"(b0), "r"(b1));
}

// two-level bf16 split of a pair of floats, packed as bf16x2
__device__ __forceinline__ void split2(float x0, float x1,
                                       uint32_t& hp, uint32_t& lp) {
    asm("cvt.rn.bf16x2.f32 %0, %1, %2;" : "=r"(hp) : "f"(x1), "f"(x0));
    float h0 = __uint_as_float(hp << 16);
    float h1 = __uint_as_float(hp & 0xffff0000u);
    float l0 = x0 - h0, l1 = x1 - h1;
    asm("cvt.rn.bf16x2.f32 %0, %1, %2;" : "=r"(lp) : "f"(l1), "f"(l0));
}

// ---------------------------------------------------------------------------
// Kernel 1: fused prep — block 128: stats + resets; blocks 0..127: A split
// ---------------------------------------------------------------------------
__global__ void prep_kernel(const float* __restrict__ norms,
                            const float* __restrict__ A) {
    if (blockIdx.x == 128) {
        __shared__ float red[BATCH];
        int t = threadIdx.x;
        float x = fminf(fmaxf(norms[t], 0.001f), 100.0f);
        red[t] = x;
        __syncthreads();
        for (int s = BATCH / 2; s > 0; s >>= 1) {
            if (t < s) red[t] += red[t + s];
            __syncthreads();
        }
        float mean = red[0] * (1.0f / BATCH);
        __syncthreads();
        float dv = x - mean;
        red[t] = dv * dv;
        __syncthreads();
        for (int s = BATCH / 2; s > 0; s >>= 1) {
            if (t < s) red[t] += red[t + s];
            __syncthreads();
        }
        float stdv = sqrtf(red[0] / (float)(BATCH - 1));  // ddof=1
        float ms = fminf(fmaxf((x - mean) / (stdv + EPS_C) * H_C, -1.0f), 1.0f);
        d_ms[t]   = ms;
        d_gang[t] = -M_C * ms;
        d_gadd[t] = M_C + M_C * ms;
        d_arg[t]  = 0ull;
    } else {
        int i = blockIdx.x * 512 + threadIdx.x;  // 65536 float4s
        float4 v = ((const float4*)A)[i];
        uint32_t h0, l0, h1, l1;
        split2(v.x, v.y, h0, l0);
        split2(v.z, v.w, h1, l1);
        ((uint2*)d_Ah)[i] = make_uint2(h0, h1);
        ((uint2*)d_Al)[i] = make_uint2(l0, l1);
    }
}

// ---------------------------------------------------------------------------
// Kernel 2: HMMA 3-split GEMM (128x64 tile, 2 CTAs/SM, 4x2 warp grid)
//           + margins + argmax
// ---------------------------------------------------------------------------
__global__ void __launch_bounds__(NT, 2)
gemm_kernel(const float* __restrict__ B, const int* __restrict__ label,
            float* __restrict__ out1, float* __restrict__ out2, int N)
{
    extern __shared__ char smem[];
    const uint32_t sb = smem_u32(smem);
    const int tid  = threadIdx.x;
    const int wid  = tid >> 5, lane = tid & 31;
    const int wm   = wid & 3;        // m quarter (32 rows)
    const int wn   = wid >> 2;       // n half (32 cols)
    const int m0   = blockIdx.x * BM;
    const int n0   = blockIdx.y * BN;

    int*   lab_s  = (int*)(smem + SM_LAB);
    float* gang_s = (float*)(smem + SM_GANG);
    float* gadd_s = (float*)(smem + SM_GADD);
    float* red_s  = (float*)(smem + SM_RED);
    float* invn_s = (float*)(smem + SM_INV);
    unsigned long long* amx = (unsigned long long*)(smem + SM_AMX);

    if (tid < BM) {
        lab_s[tid]  = label[m0 + tid];
        gang_s[tid] = d_gang[m0 + tid];
        gadd_s[tid] = d_gadd[m0 + tid];
    }

    // B loading role: column (tid&63), k-quarter (tid>>6) -> 16 rows
    const int ncl = tid & 63;
    const int col = n0 + ncl;
    const bool cv = col < N;
    const int kq  = tid >> 6;
    const float* bp = B + (size_t)(kq * 16) * N + col;

    float rb[16];
    float sumsq = 0.0f;

    auto loadB = [&](int c) {
        const float* p = bp + (size_t)(c * BK) * N;
        if (cv) {
#pragma unroll
            for (int j = 0; j < 16; j++) rb[j] = __ldg(p + (size_t)j * N);
        } else {
#pragma unroll
            for (int j = 0; j < 16; j++) rb[j] = 0.0f;
        }
    };
    auto putB = [&](int s) {
#pragma unroll
        for (int q = 0; q < 2; q++) {
            uint32_t hp[4], lp[4];
#pragma unroll
            for (int e = 0; e < 4; e++) {
                float x0 = rb[q * 8 + 2 * e], x1 = rb[q * 8 + 2 * e + 1];
                sumsq += x0 * x0 + x1 * x1;
                split2(x0, x1, hp[e], lp[e]);
            }
            uint32_t off = SWZ(ncl * 128 + (kq * 2 + q) * 16);
            *(uint4*)(smem + SM_BH(s) + off) = make_uint4(hp[0], hp[1], hp[2], hp[3]);
            *(uint4*)(smem + SM_BL(s) + off) = make_uint4(lp[0], lp[1], lp[2], lp[3]);
        }
    };
    auto cpA = [&](int c, int s) {
#pragma unroll
        for (int q = 0; q < 4; q++) {
            int id = q * 256 + tid;
            int row = id >> 3, ch = id & 7;
            uint32_t off = SWZ(row * 128 + ch * 16);
            const size_t g = (size_t)(m0 + row) * EMB + c * BK + ch * 8;
            cp16(sb + SM_AH(s) + off, d_Ah + g);
            cp16(sb + SM_AL(s) + off, d_Al + g);
        }
        CP_COMMIT();
    };

    // prologue
    loadB(0);
    cpA(0, 0);
    putB(0);
    CP_WAIT0();
    __syncthreads();

    float acc[2][4][4];
#pragma unroll
    for (int i = 0; i < 2; i++)
#pragma unroll
        for (int j = 0; j < 4; j++)
#pragma unroll
            for (int e = 0; e < 4; e++) acc[i][j][e] = 0.0f;

    // ldmatrix lane address pattern (16 rows x 32B k-window)
    const int arow = ((lane >> 3) & 1) * 8 + (lane & 7);
    const int akb  = (lane >> 4) * 16;

    for (int c = 0; c < KCH; c++) {
        const int s = c & 1, s2 = (c + 1) & 1;
        if (c < KCH - 1) {
            cpA(c + 1, s2);
            loadB(c + 1);
        }
#pragma unroll
        for (int ks = 0; ks < 4; ks++) {
            // batch-load ALL frags for this k-step (8 LDSM4), then 24 MMAs
            // LDSM4: r0=(lo8,kLo) r1=(hi8,kLo) r2=(lo8,kHi) r3=(hi8,kHi)
            uint32_t bh[2][4], bl[2][4];
#pragma unroll
            for (int jp = 0; jp < 2; jp++) {
                uint32_t off = SWZ((wn * 32 + jp * 16 + arow) * 128 + ks * 32 + akb);
                LDSM4(bh[jp], sb + SM_BH(s) + off);
                LDSM4(bl[jp], sb + SM_BL(s) + off);
            }
            uint32_t ah[2][4], al[2][4];
#pragma unroll
            for (int i = 0; i < 2; i++) {
                uint32_t off = SWZ((wm * 32 + i * 16 + arow) * 128 + ks * 32 + akb);
                LDSM4(ah[i], sb + SM_AH(s) + off);
                LDSM4(al[i], sb + SM_AL(s) + off);
            }
            // term-major: accumulator chain distance = 8
#pragma unroll
            for (int i = 0; i < 2; i++)
#pragma unroll
                for (int j = 0; j < 4; j++)
                    mma16816(acc[i][j], ah[i],
                             bh[j >> 1][j & 1], bh[j >> 1][(j & 1) + 2]);
#pragma unroll
            for (int i = 0; i < 2; i++)
#pragma unroll
                for (int j = 0; j < 4; j++)
                    mma16816(acc[i][j], ah[i],
                             bl[j >> 1][j & 1], bl[j >> 1][(j & 1) + 2]);
#pragma unroll
            for (int i = 0; i < 2; i++)
#pragma unroll
                for (int j = 0; j < 4; j++)
                    mma16816(acc[i][j], al[i],
                             bh[j >> 1][j & 1], bh[j >> 1][(j & 1) + 2]);
        }
        if (c < KCH - 1) {
            putB(s2);
            CP_WAIT0();
        }
        __syncthreads();
    }

    // column inv-norms (4 k-quarter contributions per column)
    red_s[tid] = sumsq;
    __syncthreads();
    if (tid < BN)
        invn_s[tid] = rsqrtf(fmaxf(red_s[tid] + red_s[tid + 64] +
                                   red_s[tid + 128] + red_s[tid + 192], 1e-30f));
    __syncthreads();

    // ---- epilogue: margins + stores + argmax ----
#pragma unroll
    for (int i = 0; i < 2; i++) {
        const int r0 = wm * 32 + i * 16 + (lane >> 2);
#pragma unroll
        for (int rh = 0; rh < 2; rh++) {
            const int row = r0 + rh * 8;
            const int gm  = m0 + row;
            const int lab   = lab_s[row];
            const float gng = gang_s[row];
            const float gad = gadd_s[row];
            unsigned long long best = 0ull;
#pragma unroll
            for (int j = 0; j < 4; j++) {
                const int cl0 = wn * 32 + j * 8 + (lane & 3) * 2;
                const int gc0 = n0 + cl0;
                float o1v[2], o2v[2];
#pragma unroll
                for (int e = 0; e < 2; e++) {
                    float v = acc[i][j][rh * 2 + e] * invn_s[cl0 + e];
                    float cosv = fminf(fmaxf(v, -1.0f + EPS_C), 1.0f - EPS_C);
                    float vm = cosv, o1 = cosv * S_C;
                    if (gc0 + e == lab) {  // clip(acos+g) identity off-label
                        float th = fminf(fmaxf(acosf(cosv) + gng, EPS_C),
                                         PI_C - EPS_C);
                        vm = cosf(th);
                        o1 = (vm - gad) * S_C;
                    }
                    o1v[e] = o1;
                    o2v[e] = vm * S_C;
                    if (gc0 + e < N) {
                        unsigned u = __float_as_uint(vm);
                        u = (u & 0x80000000u) ? ~u : (u | 0x80000000u);
                        unsigned long long key =
                            ((unsigned long long)u << 32) |
                            (unsigned)(~(unsigned)(gc0 + e));
                        best = best > key ? best : key;
                    }
                }
                if (gc0 + 1 < N) {
                    const size_t gb = (size_t)gm * N + gc0;
                    __stcs((float2*)(out1 + gb), make_float2(o1v[0], o1v[1]));
                    __stcs((float2*)(out2 + gb), make_float2(o2v[0], o2v[1]));
                }
            }
            unsigned long long o = __shfl_xor_sync(0xFFFFFFFFu, best, 1);
            best = best > o ? best : o;
            o = __shfl_xor_sync(0xFFFFFFFFu, best, 2);
            best = best > o ? best : o;
            if ((lane & 3) == 0) amx[row * 2 + wn] = best;
        }
    }
    __syncthreads();
    if (tid < BM) {
        unsigned long long b0 = amx[tid * 2 + 0], b1 = amx[tid * 2 + 1];
        atomicMax(&d_arg[m0 + tid], b0 > b1 ? b0 : b1);
    }
}

// ---------------------------------------------------------------------------
// Kernel 3: second margin at per-row argmax; write argmax/ms outputs
// ---------------------------------------------------------------------------
__global__ void fixup_kernel(float* __restrict__ out2,
                             float* __restrict__ oarg,
                             float* __restrict__ oms, int N) {
    int b = threadIdx.x;
    unsigned long long key = d_arg[b];
    unsigned hi = (unsigned)(key >> 32);
    unsigned lo = (unsigned)key;
    int col = (int)(~lo);
    float v = (hi & 0x80000000u) ? __uint_as_float(hi & 0x7FFFFFFFu)
                                 : __uint_as_float(~hi);
    float th = fminf(fmaxf(acosf(v) + d_gang[b], EPS_C), PI_C - EPS_C);
    out2[(size_t)b * N + col] = (cosf(th) - d_gadd[b]) * S_C;
    oarg[b] = (float)col;
    oms[b]  = d_ms[b];
}

// ---------------------------------------------------------------------------
extern "C" void kernel_launch(void* const* d_in, const int* in_sizes, int n_in,
                              void* d_out, int out_size) {
    const float* emb   = (const float*)d_in[0];
    const float* norms = (const float*)d_in[1];
    const int*   label = (const int*)d_in[2];
    const float* kern  = (const float*)d_in[3];
    int N = in_sizes[3] / EMB;

    float* out1 = (float*)d_out;
    float* out2 = out1 + (size_t)BATCH * N;
    float* oarg = out2 + (size_t)BATCH * N;
    float* oms  = oarg + BATCH;

    cudaFuncSetAttribute(gemm_kernel,
                         cudaFuncAttributeMaxDynamicSharedMemorySize, SMEM_BYTES);

    prep_kernel<<<129, 512>>>(norms, emb);
    dim3 grid(BATCH / BM, (N + BN - 1) / BN);   // x = M fast -> B tile L2 reuse
    gemm_kernel<<<grid, NT, SMEM_BYTES>>>(kern, label, out1, out2, N);
    fixup_kernel<<<1, BATCH>>>(out2, oarg, oms, N);
}